// round 1
// baseline (speedup 1.0000x reference)
#include <cuda_runtime.h>
#include <cstdint>

// ---------------------------------------------------------------------------
// RelNet forward, GB300.
//  N=64 batches, C=64 ch, 8x8 map -> O=64 objects, D=66, E=256, G=256.
//  Key factorization: layer-1 GEMM over the concatenated pair features splits
//  into  rowA[n,i,:] + rowB[n,j,:] + qc[n,:]  (tiny GEMMs), then layers 2-4
//  are fused per 128-pair tile with tf32 tensor MMA, mean-pooled, then a tiny
//  f-MLP + log_softmax.
// ---------------------------------------------------------------------------

#define NB   64
#define OO   64          // objects
#define GD   256         // hidden dim
#define DD   66          // C + 2
#define NCTA 2048        // 64 batches * 32 row tiles
#define A_STRIDE 260     // 256 + 4 pad  (conflict-free A-fragment loads)
#define B_STRIDE 264     // 256 + 8 pad  (conflict-free B-fragment loads)
#define KC   32          // k-chunk rows of weight staged per cp.async group
#define SMEM_FLOATS (128*A_STRIDE + 2*KC*B_STRIDE)
#define SMEM_BYTES  (SMEM_FLOATS * 4)

// --------------------------- device scratch --------------------------------
__device__ float d_rowA[NB*OO*GD];       // cells @ g_w1[0:66]
__device__ float d_rowB[NB*OO*GD];       // cells @ g_w1[66:132]
__device__ float d_qc  [NB*GD];          // ques  @ g_w1[132:388] + g_b1
__device__ float d_w2r [GD*GD];          // tf32-rounded weights
__device__ float d_w3r [GD*GD];
__device__ float d_w4r [GD*GD];
__device__ float d_partial[NCTA*GD];     // per-CTA column sums (deterministic)

__device__ __forceinline__ float tf32r(float x) {
    unsigned u;
    asm("cvt.rna.tf32.f32 %0, %1;" : "=r"(u) : "f"(x));
    return __uint_as_float(u);
}

__device__ __forceinline__ void mma_tf32(float* c, const unsigned* a, const unsigned* b) {
    asm volatile(
        "mma.sync.aligned.m16n8k8.row.col.f32.tf32.tf32.f32 "
        "{%0,%1,%2,%3}, {%4,%5,%6,%7}, {%8,%9}, {%0,%1,%2,%3};"
        : "+f"(c[0]), "+f"(c[1]), "+f"(c[2]), "+f"(c[3])
        : "r"(a[0]), "r"(a[1]), "r"(a[2]), "r"(a[3]),
          "r"(b[0]), "r"(b[1]));
}

// ---------------------------------------------------------------------------
// Kernel 1: factorized layer-1 pieces + tf32 weight pre-rounding.
// grid 64 (one CTA per batch), 256 threads (one per g).
// ---------------------------------------------------------------------------
__global__ void rn_pre(const float* __restrict__ img, const float* __restrict__ ques,
                       const float* __restrict__ gw1, const float* __restrict__ gb1,
                       const float* __restrict__ w2, const float* __restrict__ w3,
                       const float* __restrict__ w4) {
    __shared__ float csm[DD][OO];
    __shared__ float qsm[GD];
    const int n = blockIdx.x;
    const int t = threadIdx.x;

    for (int idx = t; idx < DD*OO; idx += 256) {
        int d = idx >> 6, i = idx & 63;
        float v;
        if (d < 64)       v = img[(n*64 + d)*64 + i];
        else if (d == 64) v = (float)(i >> 3);
        else              v = (float)(i & 7);
        csm[d][i] = v;
    }
    qsm[t] = ques[n*GD + t];
    __syncthreads();

    const int g = t;
    // rowA / rowB: 8 objects per i-tile keeps weight re-reads low.
    for (int it = 0; it < 8; ++it) {
        float accA[8], accB[8];
        #pragma unroll
        for (int ii = 0; ii < 8; ++ii) { accA[ii] = 0.f; accB[ii] = 0.f; }
        for (int d = 0; d < DD; ++d) {
            float wa = gw1[d*GD + g];
            float wb = gw1[(DD + d)*GD + g];
            #pragma unroll
            for (int ii = 0; ii < 8; ++ii) {
                float c = csm[d][it*8 + ii];
                accA[ii] += c * wa;
                accB[ii] += c * wb;
            }
        }
        #pragma unroll
        for (int ii = 0; ii < 8; ++ii) {
            int i = it*8 + ii;
            d_rowA[(n*OO + i)*GD + g] = accA[ii];
            d_rowB[(n*OO + i)*GD + g] = accB[ii];
        }
    }

    // qc = ques @ W_c + b1
    {
        float acc = gb1[g];
        for (int e = 0; e < GD; ++e)
            acc += qsm[e] * gw1[(2*DD + e)*GD + g];
        d_qc[n*GD + g] = acc;
    }

    // tf32-round weights once (round-to-nearest, avoids HW-truncation bias)
    const int gt = n*256 + t;
    for (int idx = gt; idx < GD*GD; idx += NB*256) {
        d_w2r[idx] = tf32r(w2[idx]);
        d_w3r[idx] = tf32r(w3[idx]);
        d_w4r[idx] = tf32r(w4[idx]);
    }
}

// ---------------------------------------------------------------------------
// Kernel 2: fused layers 2-4 over a 128-pair tile + column sum.
// grid 2048 (= 64 batches * 32 tiles of 2 i-rows x 64 j), 512 threads.
// warp grid: 2 (rows of 64) x 8 (cols of 32); warp tile 64x32 via 4x4 mma.
// ---------------------------------------------------------------------------
__global__ void __launch_bounds__(512, 1)
rn_main(const float* __restrict__ b2, const float* __restrict__ b3,
        const float* __restrict__ b4) {
    extern __shared__ float smem[];
    float* Asm = smem;                      // [128][A_STRIDE]
    float* Bsm = smem + 128*A_STRIDE;       // [2][KC][B_STRIDE]

    const int n    = blockIdx.x >> 5;
    const int i0   = (blockIdx.x & 31) << 1;
    const int tid  = threadIdx.x;
    const int lane = tid & 31;
    const int warp = tid >> 5;
    const int wm   = warp >> 3;             // 0..1
    const int wn   = warp & 7;              // 0..7

    // ---- stage 1: build h1 = relu(rowA_i + rowB_j + qc), tf32-rounded ----
    {
        const int g  = tid & 255;
        const int r0 = tid >> 8;            // 0 or 1
        const float qv  = d_qc[n*GD + g];
        const float a0v = d_rowA[(n*OO + i0    )*GD + g] + qv;
        const float a1v = d_rowA[(n*OO + i0 + 1)*GD + g] + qv;
        #pragma unroll 4
        for (int s = 0; s < 64; ++s) {
            int r = r0 + 2*s;
            int j = r & 63;
            float v = ((r < 64) ? a0v : a1v) + d_rowB[(n*OO + j)*GD + g];
            Asm[r*A_STRIDE + g] = tf32r(fmaxf(v, 0.f));
        }
    }
    __syncthreads();

    // ---- layers 2..4 ----
    #pragma unroll
    for (int layer = 0; layer < 3; ++layer) {
        const float* W    = (layer == 0) ? d_w2r : (layer == 1) ? d_w3r : d_w4r;
        const float* bias = (layer == 0) ? b2    : (layer == 1) ? b3    : b4;

        float C[4][4][4];
        #pragma unroll
        for (int mt = 0; mt < 4; ++mt)
            #pragma unroll
            for (int nt = 0; nt < 4; ++nt)
                #pragma unroll
                for (int q = 0; q < 4; ++q) C[mt][nt][q] = 0.f;

        // prefetch weight chunk 0
        {
            const float* src = W;
            #pragma unroll
            for (int q = 0; q < 4; ++q) {
                int idx = q*512 + tid;
                int r = idx >> 6, c = (idx & 63) << 2;
                unsigned sa = (unsigned)__cvta_generic_to_shared(Bsm + r*B_STRIDE + c);
                asm volatile("cp.async.ca.shared.global [%0], [%1], 16;"
                             :: "r"(sa), "l"(src + r*256 + c));
            }
            asm volatile("cp.async.commit_group;");
        }

        #pragma unroll 1
        for (int ch = 0; ch < 8; ++ch) {
            if (ch < 7) {
                const float* src = W + (ch + 1)*KC*256;
                float* dst = Bsm + ((ch + 1) & 1)*(KC*B_STRIDE);
                #pragma unroll
                for (int q = 0; q < 4; ++q) {
                    int idx = q*512 + tid;
                    int r = idx >> 6, c = (idx & 63) << 2;
                    unsigned sa = (unsigned)__cvta_generic_to_shared(dst + r*B_STRIDE + c);
                    asm volatile("cp.async.ca.shared.global [%0], [%1], 16;"
                                 :: "r"(sa), "l"(src + r*256 + c));
                }
                asm volatile("cp.async.commit_group;");
                asm volatile("cp.async.wait_group 1;");
            } else {
                asm volatile("cp.async.wait_group 0;");
            }
            __syncthreads();

            const float* Bb = Bsm + (ch & 1)*(KC*B_STRIDE);
            #pragma unroll
            for (int k8 = 0; k8 < 4; ++k8) {
                const int kb = k8*8;
                unsigned a[4][4];
                #pragma unroll
                for (int mt = 0; mt < 4; ++mt) {
                    const float* ap = Asm + (wm*64 + mt*16 + (lane >> 2))*A_STRIDE
                                          + (ch*KC + kb + (lane & 3));
                    a[mt][0] = __float_as_uint(ap[0]);
                    a[mt][1] = __float_as_uint(ap[8*A_STRIDE]);
                    a[mt][2] = __float_as_uint(ap[4]);
                    a[mt][3] = __float_as_uint(ap[8*A_STRIDE + 4]);
                }
                unsigned bf[4][2];
                #pragma unroll
                for (int nt = 0; nt < 4; ++nt) {
                    const float* bp = Bb + (kb + (lane & 3))*B_STRIDE
                                         + (wn*32 + nt*8 + (lane >> 2));
                    bf[nt][0] = __float_as_uint(bp[0]);
                    bf[nt][1] = __float_as_uint(bp[4*B_STRIDE]);
                }
                #pragma unroll
                for (int mt = 0; mt < 4; ++mt)
                    #pragma unroll
                    for (int nt = 0; nt < 4; ++nt)
                        mma_tf32(C[mt][nt], a[mt], bf[nt]);
            }
            __syncthreads();
        }

        // epilogue: bias + relu, in-place into Asm (C fully in regs; barrier
        // above guarantees all A reads finished).
        #pragma unroll
        for (int mt = 0; mt < 4; ++mt) {
            #pragma unroll
            for (int nt = 0; nt < 4; ++nt) {
                int row = wm*64 + mt*16 + (lane >> 2);
                int col = wn*32 + nt*8 + (lane & 3)*2;
                float b0v = bias[col], b1v = bias[col + 1];
                float v00 = fmaxf(C[mt][nt][0] + b0v, 0.f);
                float v01 = fmaxf(C[mt][nt][1] + b1v, 0.f);
                float v10 = fmaxf(C[mt][nt][2] + b0v, 0.f);
                float v11 = fmaxf(C[mt][nt][3] + b1v, 0.f);
                if (layer < 2) {                 // next layer consumes as tf32
                    v00 = tf32r(v00); v01 = tf32r(v01);
                    v10 = tf32r(v10); v11 = tf32r(v11);
                }
                Asm[ row     *A_STRIDE + col    ] = v00;
                Asm[ row     *A_STRIDE + col + 1] = v01;
                Asm[(row + 8)*A_STRIDE + col    ] = v10;
                Asm[(row + 8)*A_STRIDE + col + 1] = v11;
            }
        }
        __syncthreads();
    }

    // ---- deterministic column sum of the 128x256 tile ----
    {
        const int col  = tid & 255;
        const int half = tid >> 8;
        float s = 0.f;
        const int rbase = half*64;
        #pragma unroll 8
        for (int r = 0; r < 64; ++r)
            s += Asm[(rbase + r)*A_STRIDE + col];
        Bsm[half*GD + col] = s;
        __syncthreads();
        if (tid < 256)
            d_partial[blockIdx.x*GD + tid] = Bsm[tid] + Bsm[GD + tid];
    }
}

// ---------------------------------------------------------------------------
// Kernel 3: mean -> f-MLP -> log_softmax. grid 64, 256 threads.
// ---------------------------------------------------------------------------
__global__ void rn_post(const float* __restrict__ fw1, const float* __restrict__ fb1,
                        const float* __restrict__ fw2, const float* __restrict__ fb2,
                        const float* __restrict__ fw3, const float* __restrict__ fb3,
                        float* __restrict__ out) {
    __shared__ float ctx[GD], y1s[GD], y2s[GD], red[16];
    const int n = blockIdx.x;
    const int t = threadIdx.x;

    float s = 0.f;
    for (int p = 0; p < 32; ++p)
        s += d_partial[(n*32 + p)*GD + t];
    ctx[t] = s * (1.0f/4096.0f);
    __syncthreads();

    float a = fb1[t];
    for (int k = 0; k < GD; ++k) a += ctx[k] * fw1[k*GD + t];
    y1s[t] = fmaxf(a, 0.f);
    __syncthreads();

    float b = fb2[t];
    for (int k = 0; k < GD; ++k) b += y1s[k] * fw2[k*GD + t];
    y2s[t] = fmaxf(b, 0.f);
    __syncthreads();

    float p0 = y2s[t] * fw3[t*2 + 0];
    float p1 = y2s[t] * fw3[t*2 + 1];
    #pragma unroll
    for (int o = 16; o > 0; o >>= 1) {
        p0 += __shfl_down_sync(0xffffffffu, p0, o);
        p1 += __shfl_down_sync(0xffffffffu, p1, o);
    }
    if ((t & 31) == 0) { red[t >> 5] = p0; red[8 + (t >> 5)] = p1; }
    __syncthreads();
    if (t == 0) {
        float s0 = fb3[0], s1 = fb3[1];
        for (int w = 0; w < 8; ++w) { s0 += red[w]; s1 += red[8 + w]; }
        float m   = fmaxf(s0, s1);
        float lse = m + logf(expf(s0 - m) + expf(s1 - m));
        out[n*2 + 0] = s0 - lse;
        out[n*2 + 1] = s1 - lse;
    }
}

// ---------------------------------------------------------------------------
extern "C" void kernel_launch(void* const* d_in, const int* in_sizes, int n_in,
                              void* d_out, int out_size) {
    (void)in_sizes; (void)n_in; (void)out_size;
    const float* img  = (const float*)d_in[0];
    const float* ques = (const float*)d_in[1];
    const float* gw1  = (const float*)d_in[2];
    const float* gb1  = (const float*)d_in[3];
    const float* gw2  = (const float*)d_in[4];
    const float* gb2  = (const float*)d_in[5];
    const float* gw3  = (const float*)d_in[6];
    const float* gb3  = (const float*)d_in[7];
    const float* gw4  = (const float*)d_in[8];
    const float* gb4  = (const float*)d_in[9];
    const float* fw1  = (const float*)d_in[10];
    const float* fb1  = (const float*)d_in[11];
    const float* fw2  = (const float*)d_in[12];
    const float* fb2  = (const float*)d_in[13];
    const float* fw3  = (const float*)d_in[14];
    const float* fb3  = (const float*)d_in[15];
    float* out = (float*)d_out;

    cudaFuncSetAttribute(rn_main, cudaFuncAttributeMaxDynamicSharedMemorySize, SMEM_BYTES);

    rn_pre <<<NB,   256>>>(img, ques, gw1, gb1, gw2, gw3, gw4);
    rn_main<<<NCTA, 512, SMEM_BYTES>>>(gb2, gb3, gb4);
    rn_post<<<NB,   256>>>(fw1, fb1, fw2, fb2, fw3, fb3, out);
}

// round 2
// speedup vs baseline: 2.0184x; 2.0184x over previous
#include <cuda_runtime.h>
#include <cuda_bf16.h>
#include <cstdint>

// ---------------------------------------------------------------------------
// RelNet forward, GB300 (sm_103a).
// Layer-1 factorization: h1(n,i,j) = relu(rowA[n,i] + rowB[n,j] + qc[n]).
// Layers 2-4: fused bf16 tensor-core GEMMs (m16n8k16 + ldmatrix) per
// 128-pair tile, activations resident in SMEM, fp32 column sums -> mean
// -> fp32 f-MLP -> log_softmax.
// ---------------------------------------------------------------------------

#define NB   64
#define OO   64
#define GD   256
#define DD   66
#define NCTA 2048
#define AS   264                     // bf16 elems per smem row (256 + 8 pad)
#define SM_MAIN (3*128*AS*2)         // A tile + 2 weight half-buffers (bytes)
#define SM_PRE  ((132*256 + 66*64 + 256)*4)

// --------------------------- device scratch --------------------------------
__device__ float d_rowA[NB*OO*GD];
__device__ float d_rowB[NB*OO*GD];
__device__ float d_qc  [NB*GD];
__device__ __nv_bfloat16 d_w2b[GD*GD];
__device__ __nv_bfloat16 d_w3b[GD*GD];
__device__ __nv_bfloat16 d_w4b[GD*GD];
__device__ float d_partial[NCTA*GD];

__device__ __forceinline__ void ldsm_x4(unsigned* r, unsigned addr) {
    asm volatile("ldmatrix.sync.aligned.m8n8.x4.shared.b16 {%0,%1,%2,%3}, [%4];"
                 : "=r"(r[0]), "=r"(r[1]), "=r"(r[2]), "=r"(r[3]) : "r"(addr));
}
__device__ __forceinline__ void ldsm_x4_t(unsigned* r, unsigned addr) {
    asm volatile("ldmatrix.sync.aligned.m8n8.x4.trans.shared.b16 {%0,%1,%2,%3}, [%4];"
                 : "=r"(r[0]), "=r"(r[1]), "=r"(r[2]), "=r"(r[3]) : "r"(addr));
}
__device__ __forceinline__ void mma_bf16(float* c, const unsigned* a,
                                         unsigned b0, unsigned b1) {
    asm volatile(
        "mma.sync.aligned.m16n8k16.row.col.f32.bf16.bf16.f32 "
        "{%0,%1,%2,%3}, {%4,%5,%6,%7}, {%8,%9}, {%0,%1,%2,%3};"
        : "+f"(c[0]), "+f"(c[1]), "+f"(c[2]), "+f"(c[3])
        : "r"(a[0]), "r"(a[1]), "r"(a[2]), "r"(a[3]), "r"(b0), "r"(b1));
}

// ---------------------------------------------------------------------------
// Weight fp32 -> bf16 conversion. grid 96 x 1024, 2 elems/thread.
// ---------------------------------------------------------------------------
__global__ void rn_wconv(const float* __restrict__ w2, const float* __restrict__ w3,
                         const float* __restrict__ w4) {
    int gt = blockIdx.x * 1024 + threadIdx.x;        // 0 .. 98303
    int m   = gt >> 15;                               // 0..2
    int off = (gt & 32767) * 2;
    const float* src = (m == 0) ? w2 : (m == 1) ? w3 : w4;
    __nv_bfloat16* dst = (m == 0) ? d_w2b : (m == 1) ? d_w3b : d_w4b;
    float2 v = *(const float2*)(src + off);
    *(__nv_bfloat162*)(dst + off) = __floats2bfloat162_rn(v.x, v.y);
}

// ---------------------------------------------------------------------------
// rn_pre: rowA/rowB/qc (all fp32, exact). grid 64, 512 threads.
// g_w1[0:132] slab staged in SMEM to kill the L2 latency chain.
// ---------------------------------------------------------------------------
__global__ void __launch_bounds__(512, 1)
rn_pre(const float* __restrict__ img, const float* __restrict__ ques,
       const float* __restrict__ gw1, const float* __restrict__ gb1) {
    extern __shared__ float fsm[];
    float* wsm = fsm;                 // [132][256]
    float* csm = fsm + 132*256;       // [66][64]
    float* qsm = csm + 66*64;         // [256]
    const int n = blockIdx.x;
    const int t = threadIdx.x;

    for (int i = t; i < 132*256/4; i += 512)
        ((float4*)wsm)[i] = ((const float4*)gw1)[i];
    for (int idx = t; idx < DD*OO; idx += 512) {
        int d = idx >> 6, i = idx & 63;
        float v;
        if (d < 64)       v = img[(n*64 + d)*64 + i];
        else if (d == 64) v = (float)(i >> 3);
        else              v = (float)(i & 7);
        csm[d*64 + i] = v;
    }
    if (t < 256) qsm[t] = ques[n*GD + t];
    __syncthreads();

    const int half = t >> 8;                   // 0: rowA, 1: rowB
    const int g    = t & 255;
    float* out = half ? d_rowB : d_rowA;
    const float* wb = wsm + half*DD*256;

    for (int it = 0; it < 8; ++it) {
        float acc[8];
        #pragma unroll
        for (int ii = 0; ii < 8; ++ii) acc[ii] = 0.f;
        #pragma unroll 2
        for (int d = 0; d < DD; ++d) {
            float w = wb[d*256 + g];
            #pragma unroll
            for (int ii = 0; ii < 8; ++ii)
                acc[ii] += csm[d*64 + it*8 + ii] * w;
        }
        #pragma unroll
        for (int ii = 0; ii < 8; ++ii)
            out[(n*OO + it*8 + ii)*GD + g] = acc[ii];
    }

    if (half) {   // qc = ques @ W_c + b1 (fp32)
        float acc = gb1[g];
        #pragma unroll 4
        for (int e = 0; e < GD; ++e)
            acc += qsm[e] * gw1[(2*DD + e)*GD + g];
        d_qc[n*GD + g] = acc;
    }
}

// ---------------------------------------------------------------------------
// rn_main: fused layers 2-4 per 128-pair tile. grid 2048, 512 threads.
// A tile 128x256 bf16 in smem; weights double-buffered in k=128 halves.
// Warp grid 2x8, warp tile 64x32, mma m16n8k16 bf16 via ldmatrix.
// ---------------------------------------------------------------------------
__global__ void __launch_bounds__(512, 1)
rn_main(const float* __restrict__ b2, const float* __restrict__ b3,
        const float* __restrict__ b4) {
    extern __shared__ __nv_bfloat16 sm[];
    __nv_bfloat16* Asm = sm;                      // [128][AS]
    __nv_bfloat16* Bsm = sm + 128*AS;             // 2 x [128][AS]
    const unsigned AsmS = (unsigned)__cvta_generic_to_shared(Asm);
    const unsigned BsmS = (unsigned)__cvta_generic_to_shared(Bsm);

    const int n    = blockIdx.x >> 5;
    const int i0   = (blockIdx.x & 31) << 1;
    const int tid  = threadIdx.x;
    const int lane = tid & 31;
    const int warp = tid >> 5;
    const int wm   = warp >> 3;                   // 0..1 -> 64-row block
    const int wn   = warp & 7;                    // 0..7 -> 32-col block

    // chunk c (0..5): layer c/2, k-half c&1
    auto issue = [&](int c) {
        const __nv_bfloat16* W = (c < 2) ? d_w2b : (c < 4) ? d_w3b : d_w4b;
        const __nv_bfloat16* src = W + (c & 1) * 128 * GD;
        unsigned dst = BsmS + (unsigned)((c & 1) * 128 * AS * 2);
        #pragma unroll
        for (int q = 0; q < 8; ++q) {
            int idx = q * 512 + tid;
            int r = idx >> 5, s = idx & 31;
            unsigned sa = dst + (unsigned)(r * AS + s * 8) * 2u;
            asm volatile("cp.async.cg.shared.global [%0], [%1], 16;"
                         :: "r"(sa), "l"(src + r * GD + s * 8));
        }
        asm volatile("cp.async.commit_group;");
    };

    issue(0);   // prefetch first weight half while building h1

    // ---- stage 1: h1 = relu(rowA_i + rowB_j + qc) -> bf16 A tile ----
    {
        const int c2 = tid & 127;                 // col pair
        const int g  = c2 * 2;
        const int r0 = tid >> 7;                  // 0..3
        const float2 qv = *(const float2*)(d_qc + n*GD + g);
        float2 A0 = *(const float2*)(d_rowA + (n*OO + i0    )*GD + g);
        float2 A1 = *(const float2*)(d_rowA + (n*OO + i0 + 1)*GD + g);
        A0.x += qv.x; A0.y += qv.y; A1.x += qv.x; A1.y += qv.y;
        #pragma unroll 4
        for (int s = 0; s < 32; ++s) {
            int r = r0 + s*4;
            int j = r & 63;
            float2 B = *(const float2*)(d_rowB + (n*OO + j)*GD + g);
            float vx = ((r >> 6) ? A1.x : A0.x) + B.x;
            float vy = ((r >> 6) ? A1.y : A0.y) + B.y;
            *(__nv_bfloat162*)(Asm + r*AS + g) =
                __floats2bfloat162_rn(fmaxf(vx, 0.f), fmaxf(vy, 0.f));
        }
    }

    float stage_s[2];   // (unused placeholder to keep regs tidy)

    #pragma unroll 1
    for (int layer = 0; layer < 3; ++layer) {
        float C[4][4][4];
        #pragma unroll
        for (int mt = 0; mt < 4; ++mt)
            #pragma unroll
            for (int nt = 0; nt < 4; ++nt) {
                C[mt][nt][0] = 0.f; C[mt][nt][1] = 0.f;
                C[mt][nt][2] = 0.f; C[mt][nt][3] = 0.f;
            }

        #pragma unroll 1
        for (int h = 0; h < 2; ++h) {
            const int c = layer*2 + h;
            if (c < 5) { issue(c + 1); asm volatile("cp.async.wait_group 1;"); }
            else       {               asm volatile("cp.async.wait_group 0;"); }
            __syncthreads();            // chunk c ready (also orders stage-1 / epilogue A writes)

            const unsigned bufS = BsmS + (unsigned)((c & 1) * 128 * AS * 2);
            #pragma unroll
            for (int ks = 0; ks < 8; ++ks) {
                const int kb = h*128 + ks*16;
                unsigned a[4][4];
                #pragma unroll
                for (int mt = 0; mt < 4; ++mt) {
                    unsigned ad = AsmS +
                        (unsigned)(((wm*64 + mt*16 + (lane & 15)))*AS
                                   + kb + ((lane >> 4) * 8)) * 2u;
                    ldsm_x4(a[mt], ad);
                }
                unsigned bfr[2][4];
                #pragma unroll
                for (int pr = 0; pr < 2; ++pr) {
                    unsigned bd = bufS +
                        (unsigned)((ks*16 + (lane & 15))*AS
                                   + wn*32 + pr*16 + ((lane >> 4) * 8)) * 2u;
                    ldsm_x4_t(bfr[pr], bd);
                }
                #pragma unroll
                for (int mt = 0; mt < 4; ++mt) {
                    #pragma unroll
                    for (int pr = 0; pr < 2; ++pr) {
                        mma_bf16(C[mt][pr*2    ], a[mt], bfr[pr][0], bfr[pr][1]);
                        mma_bf16(C[mt][pr*2 + 1], a[mt], bfr[pr][2], bfr[pr][3]);
                    }
                }
            }
            __syncthreads();            // all reads of buf c / A done
        }

        if (layer < 2) {
            // epilogue: bias + relu -> bf16, in place into A tile
            const float* bias = (layer == 0) ? b2 : b3;
            #pragma unroll
            for (int mt = 0; mt < 4; ++mt) {
                #pragma unroll
                for (int nt = 0; nt < 4; ++nt) {
                    int row = wm*64 + mt*16 + (lane >> 2);
                    int col = wn*32 + nt*8 + (lane & 3)*2;
                    float2 bb = *(const float2*)(bias + col);
                    float v0 = fmaxf(C[mt][nt][0] + bb.x, 0.f);
                    float v1 = fmaxf(C[mt][nt][1] + bb.y, 0.f);
                    float v2 = fmaxf(C[mt][nt][2] + bb.x, 0.f);
                    float v3 = fmaxf(C[mt][nt][3] + bb.y, 0.f);
                    *(__nv_bfloat162*)(Asm + row*AS + col)     = __floats2bfloat162_rn(v0, v1);
                    *(__nv_bfloat162*)(Asm + (row+8)*AS + col) = __floats2bfloat162_rn(v2, v3);
                }
            }
            // next layer's post-wait __syncthreads orders these writes
        } else {
            // layer 4: bias + relu + column sum straight from fp32 registers
            float* stg = (float*)Asm;    // A tile dead; reuse as fp32 staging
            #pragma unroll
            for (int nt = 0; nt < 4; ++nt) {
                int col = wn*32 + nt*8 + (lane & 3)*2;
                float2 bb = *(const float2*)(b4 + col);
                float s0 = 0.f, s1 = 0.f;
                #pragma unroll
                for (int mt = 0; mt < 4; ++mt) {
                    s0 += fmaxf(C[mt][nt][0] + bb.x, 0.f)
                        + fmaxf(C[mt][nt][2] + bb.x, 0.f);
                    s1 += fmaxf(C[mt][nt][1] + bb.y, 0.f)
                        + fmaxf(C[mt][nt][3] + bb.y, 0.f);
                }
                #pragma unroll
                for (int off = 16; off >= 4; off >>= 1) {
                    s0 += __shfl_down_sync(0xffffffffu, s0, off);
                    s1 += __shfl_down_sync(0xffffffffu, s1, off);
                }
                if (lane < 4) {
                    int cc = wn*32 + nt*8 + lane*2;
                    stg[wm*GD + cc]     = s0;
                    stg[wm*GD + cc + 1] = s1;
                }
            }
            __syncthreads();
            if (tid < GD)
                d_partial[blockIdx.x*GD + tid] = stg[tid] + stg[GD + tid];
        }
    }
    (void)stage_s;
}

// ---------------------------------------------------------------------------
// rn_post: mean -> f-MLP -> log_softmax. grid 64, 256 threads. (fp32 exact)
// ---------------------------------------------------------------------------
__global__ void rn_post(const float* __restrict__ fw1, const float* __restrict__ fb1,
                        const float* __restrict__ fw2, const float* __restrict__ fb2,
                        const float* __restrict__ fw3, const float* __restrict__ fb3,
                        float* __restrict__ out) {
    __shared__ float ctx[GD], y1s[GD], y2s[GD], red[16];
    const int n = blockIdx.x;
    const int t = threadIdx.x;

    float s = 0.f;
    #pragma unroll 4
    for (int p = 0; p < 32; ++p)
        s += d_partial[(n*32 + p)*GD + t];
    ctx[t] = s * (1.0f/4096.0f);
    __syncthreads();

    float a = fb1[t];
    #pragma unroll 4
    for (int k = 0; k < GD; ++k) a += ctx[k] * fw1[k*GD + t];
    y1s[t] = fmaxf(a, 0.f);
    __syncthreads();

    float b = fb2[t];
    #pragma unroll 4
    for (int k = 0; k < GD; ++k) b += y1s[k] * fw2[k*GD + t];
    y2s[t] = fmaxf(b, 0.f);
    __syncthreads();

    float p0 = y2s[t] * fw3[t*2 + 0];
    float p1 = y2s[t] * fw3[t*2 + 1];
    #pragma unroll
    for (int o = 16; o > 0; o >>= 1) {
        p0 += __shfl_down_sync(0xffffffffu, p0, o);
        p1 += __shfl_down_sync(0xffffffffu, p1, o);
    }
    if ((t & 31) == 0) { red[t >> 5] = p0; red[8 + (t >> 5)] = p1; }
    __syncthreads();
    if (t == 0) {
        float s0 = fb3[0], s1 = fb3[1];
        for (int w = 0; w < 8; ++w) { s0 += red[w]; s1 += red[8 + w]; }
        float m   = fmaxf(s0, s1);
        float lse = m + logf(expf(s0 - m) + expf(s1 - m));
        out[n*2 + 0] = s0 - lse;
        out[n*2 + 1] = s1 - lse;
    }
}

// ---------------------------------------------------------------------------
extern "C" void kernel_launch(void* const* d_in, const int* in_sizes, int n_in,
                              void* d_out, int out_size) {
    (void)in_sizes; (void)n_in; (void)out_size;
    const float* img  = (const float*)d_in[0];
    const float* ques = (const float*)d_in[1];
    const float* gw1  = (const float*)d_in[2];
    const float* gb1  = (const float*)d_in[3];
    const float* gw2  = (const float*)d_in[4];
    const float* gb2  = (const float*)d_in[5];
    const float* gw3  = (const float*)d_in[6];
    const float* gb3  = (const float*)d_in[7];
    const float* gw4  = (const float*)d_in[8];
    const float* gb4  = (const float*)d_in[9];
    const float* fw1  = (const float*)d_in[10];
    const float* fb1  = (const float*)d_in[11];
    const float* fw2  = (const float*)d_in[12];
    const float* fb2  = (const float*)d_in[13];
    const float* fw3  = (const float*)d_in[14];
    const float* fb3  = (const float*)d_in[15];
    float* out = (float*)d_out;

    cudaFuncSetAttribute(rn_pre,  cudaFuncAttributeMaxDynamicSharedMemorySize, SM_PRE);
    cudaFuncSetAttribute(rn_main, cudaFuncAttributeMaxDynamicSharedMemorySize, SM_MAIN);

    rn_wconv<<<96, 1024>>>(gw2, gw3, gw4);
    rn_pre  <<<NB, 512, SM_PRE>>>(img, ques, gw1, gb1);
    rn_main <<<NCTA, 512, SM_MAIN>>>(gb2, gb3, gb4);
    rn_post <<<NB, 256>>>(fw1, fb1, fw2, fb2, fw3, fb3, out);
}

// round 5
// speedup vs baseline: 2.1323x; 1.0564x over previous
#include <cuda_runtime.h>
#include <cuda_bf16.h>
#include <cstdint>

// ---------------------------------------------------------------------------
// RelNet forward, GB300 (sm_103a).
// h1(n,i,j) = relu(rowA[n,i] + rowB[n,j] + qc[n])  (layer-1 factorization)
// Layers 2-4: fused bf16 m16n8k16 MMA per 128-pair tile (R2-proven config),
// fp32 column sums -> mean -> parallel f-MLP -> log_softmax.
// ---------------------------------------------------------------------------

#define NB   64
#define OO   64
#define GD   256
#define DD   66
#define NCTA 2048                    // 64 batches * 32 row tiles (2 i x 64 j)
#define AS   264                     // bf16 elems per smem row (256 + 8 pad)
#define SM_MAIN (3*128*AS*2)         // A tile + 2 weight half-buffers (bytes)
#define SM_PRE  ((132*256 + 66*64 + 256)*4)

// --------------------------- device scratch --------------------------------
__device__ float d_rowA[NB*OO*GD];
__device__ float d_rowB[NB*OO*GD];
__device__ float d_qc  [NB*GD];
__device__ __nv_bfloat16 d_w2b[GD*GD];
__device__ __nv_bfloat16 d_w3b[GD*GD];
__device__ __nv_bfloat16 d_w4b[GD*GD];
__device__ float d_partial[NCTA*GD];

__device__ __forceinline__ void ldsm_x4(unsigned* r, unsigned addr) {
    asm volatile("ldmatrix.sync.aligned.m8n8.x4.shared.b16 {%0,%1,%2,%3}, [%4];"
                 : "=r"(r[0]), "=r"(r[1]), "=r"(r[2]), "=r"(r[3]) : "r"(addr));
}
__device__ __forceinline__ void ldsm_x4_t(unsigned* r, unsigned addr) {
    asm volatile("ldmatrix.sync.aligned.m8n8.x4.trans.shared.b16 {%0,%1,%2,%3}, [%4];"
                 : "=r"(r[0]), "=r"(r[1]), "=r"(r[2]), "=r"(r[3]) : "r"(addr));
}
__device__ __forceinline__ void mma_bf16(float* c, const unsigned* a,
                                         unsigned b0, unsigned b1) {
    asm volatile(
        "mma.sync.aligned.m16n8k16.row.col.f32.bf16.bf16.f32 "
        "{%0,%1,%2,%3}, {%4,%5,%6,%7}, {%8,%9}, {%0,%1,%2,%3};"
        : "+f"(c[0]), "+f"(c[1]), "+f"(c[2]), "+f"(c[3])
        : "r"(a[0]), "r"(a[1]), "r"(a[2]), "r"(a[3]), "r"(b0), "r"(b1));
}

// ---------------------------------------------------------------------------
// rn_pre: rowA/rowB/qc (fp32 exact) + weight bf16 conversion. grid 64 x 512.
// ---------------------------------------------------------------------------
__global__ void __launch_bounds__(512, 1)
rn_pre(const float* __restrict__ img, const float* __restrict__ ques,
       const float* __restrict__ gw1, const float* __restrict__ gb1,
       const float* __restrict__ w2, const float* __restrict__ w3,
       const float* __restrict__ w4) {
    extern __shared__ float fsm[];
    float* wsm = fsm;                 // [132][256]
    float* csm = fsm + 132*256;       // [66][64]
    float* qsm = csm + 66*64;         // [256]
    const int n = blockIdx.x;
    const int t = threadIdx.x;

    for (int i = t; i < 132*256/4; i += 512)
        ((float4*)wsm)[i] = ((const float4*)gw1)[i];
    for (int idx = t; idx < DD*OO; idx += 512) {
        int d = idx >> 6, i = idx & 63;
        float v;
        if (d < 64)       v = img[(n*64 + d)*64 + i];
        else if (d == 64) v = (float)(i >> 3);
        else              v = (float)(i & 7);
        csm[d*64 + i] = v;
    }
    if (t < 256) qsm[t] = ques[n*GD + t];
    __syncthreads();

    const int half = t >> 8;
    const int g    = t & 255;
    float* out = half ? d_rowB : d_rowA;
    const float* wb = wsm + half*DD*256;

    for (int it = 0; it < 8; ++it) {
        float acc[8];
        #pragma unroll
        for (int ii = 0; ii < 8; ++ii) acc[ii] = 0.f;
        #pragma unroll 2
        for (int d = 0; d < DD; ++d) {
            float w = wb[d*256 + g];
            #pragma unroll
            for (int ii = 0; ii < 8; ++ii)
                acc[ii] += csm[d*64 + it*8 + ii] * w;
        }
        #pragma unroll
        for (int ii = 0; ii < 8; ++ii)
            out[(n*OO + it*8 + ii)*GD + g] = acc[ii];
    }

    if (half) {   // qc = ques @ W_c + b1
        float acc = gb1[g];
        #pragma unroll 4
        for (int e = 0; e < GD; ++e)
            acc += qsm[e] * gw1[(2*DD + e)*GD + g];
        d_qc[n*GD + g] = acc;
    }

    // fold in weight fp32->bf16 conversion (64*512 threads over 3*32768 float2)
    {
        const int gt = n*512 + t;                   // 0..32767
        #pragma unroll
        for (int m = 0; m < 3; ++m) {
            const float* src = (m == 0) ? w2 : (m == 1) ? w3 : w4;
            __nv_bfloat16* dst = (m == 0) ? d_w2b : (m == 1) ? d_w3b : d_w4b;
            float2 v = *(const float2*)(src + gt*2);
            *(__nv_bfloat162*)(dst + gt*2) = __floats2bfloat162_rn(v.x, v.y);
        }
    }
}

// ---------------------------------------------------------------------------
// rn_main: fused layers 2-4 per 128-pair tile. grid 2048, 512 threads.
// A tile 128x256 bf16 in smem; weights double-buffered in k=128 halves.
// Warp grid 2x8, warp tile 64x32, mma m16n8k16 bf16 via ldmatrix.
// (R2-proven configuration.)
// ---------------------------------------------------------------------------
__global__ void __launch_bounds__(512, 1)
rn_main(const float* __restrict__ b2, const float* __restrict__ b3,
        const float* __restrict__ b4) {
    extern __shared__ __nv_bfloat16 sm[];
    __nv_bfloat16* Asm = sm;                      // [128][AS]
    __nv_bfloat16* Bsm = sm + 128*AS;             // 2 x [128][AS]
    const unsigned AsmS = (unsigned)__cvta_generic_to_shared(Asm);
    const unsigned BsmS = (unsigned)__cvta_generic_to_shared(Bsm);

    const int n    = blockIdx.x >> 5;
    const int i0   = (blockIdx.x & 31) << 1;
    const int tid  = threadIdx.x;
    const int lane = tid & 31;
    const int warp = tid >> 5;
    const int wm   = warp >> 3;                   // 0..1 -> 64-row block
    const int wn   = warp & 7;                    // 0..7 -> 32-col block

    // chunk c (0..5): layer c/2, k-half c&1
    auto issue = [&](int c) {
        const __nv_bfloat16* W = (c < 2) ? d_w2b : (c < 4) ? d_w3b : d_w4b;
        const __nv_bfloat16* src = W + (c & 1) * 128 * GD;
        unsigned dst = BsmS + (unsigned)((c & 1) * 128 * AS * 2);
        #pragma unroll
        for (int q = 0; q < 8; ++q) {
            int idx = q * 512 + tid;
            int r = idx >> 5, s = idx & 31;
            unsigned sa = dst + (unsigned)(r * AS + s * 8) * 2u;
            asm volatile("cp.async.cg.shared.global [%0], [%1], 16;"
                         :: "r"(sa), "l"(src + r * GD + s * 8));
        }
        asm volatile("cp.async.commit_group;");
    };

    issue(0);   // prefetch first weight half while building h1

    // ---- stage 1: h1 = relu(rowA_i + rowB_j + qc) -> bf16 A tile ----
    {
        const int g  = (tid & 127) * 2;
        const int r0 = tid >> 7;                  // 0..3
        const float2 qv = *(const float2*)(d_qc + n*GD + g);
        float2 A0 = *(const float2*)(d_rowA + (n*OO + i0    )*GD + g);
        float2 A1 = *(const float2*)(d_rowA + (n*OO + i0 + 1)*GD + g);
        A0.x += qv.x; A0.y += qv.y; A1.x += qv.x; A1.y += qv.y;
        #pragma unroll 4
        for (int s = 0; s < 32; ++s) {
            int r = r0 + s*4;
            int j = r & 63;
            float2 B = *(const float2*)(d_rowB + (n*OO + j)*GD + g);
            float vx = ((r >> 6) ? A1.x : A0.x) + B.x;
            float vy = ((r >> 6) ? A1.y : A0.y) + B.y;
            *(__nv_bfloat162*)(Asm + r*AS + g) =
                __floats2bfloat162_rn(fmaxf(vx, 0.f), fmaxf(vy, 0.f));
        }
    }

    #pragma unroll 1
    for (int layer = 0; layer < 3; ++layer) {
        float C[4][4][4];
        #pragma unroll
        for (int mt = 0; mt < 4; ++mt)
            #pragma unroll
            for (int nt = 0; nt < 4; ++nt) {
                C[mt][nt][0] = 0.f; C[mt][nt][1] = 0.f;
                C[mt][nt][2] = 0.f; C[mt][nt][3] = 0.f;
            }

        #pragma unroll 1
        for (int h = 0; h < 2; ++h) {
            const int c = layer*2 + h;
            if (c < 5) { issue(c + 1); asm volatile("cp.async.wait_group 1;"); }
            else       {               asm volatile("cp.async.wait_group 0;"); }
            __syncthreads();            // chunk c ready; orders A-tile writes

            const unsigned bufS = BsmS + (unsigned)((c & 1) * 128 * AS * 2);
            #pragma unroll
            for (int ks = 0; ks < 8; ++ks) {
                const int kb = h*128 + ks*16;
                unsigned a[4][4];
                #pragma unroll
                for (int mt = 0; mt < 4; ++mt) {
                    unsigned ad = AsmS +
                        (unsigned)(((wm*64 + mt*16 + (lane & 15)))*AS
                                   + kb + ((lane >> 4) * 8)) * 2u;
                    ldsm_x4(a[mt], ad);
                }
                unsigned bfr[2][4];
                #pragma unroll
                for (int pr = 0; pr < 2; ++pr) {
                    unsigned bd = bufS +
                        (unsigned)((ks*16 + (lane & 15))*AS
                                   + wn*32 + pr*16 + ((lane >> 4) * 8)) * 2u;
                    ldsm_x4_t(bfr[pr], bd);
                }
                #pragma unroll
                for (int mt = 0; mt < 4; ++mt) {
                    #pragma unroll
                    for (int pr = 0; pr < 2; ++pr) {
                        mma_bf16(C[mt][pr*2    ], a[mt], bfr[pr][0], bfr[pr][1]);
                        mma_bf16(C[mt][pr*2 + 1], a[mt], bfr[pr][2], bfr[pr][3]);
                    }
                }
            }
            __syncthreads();            // all reads of buf c / A done
        }

        if (layer < 2) {
            // epilogue: bias + relu -> bf16, in place into A tile
            const float* bias = (layer == 0) ? b2 : b3;
            #pragma unroll
            for (int mt = 0; mt < 4; ++mt) {
                #pragma unroll
                for (int nt = 0; nt < 4; ++nt) {
                    int row = wm*64 + mt*16 + (lane >> 2);
                    int col = wn*32 + nt*8 + (lane & 3)*2;
                    float2 bb = *(const float2*)(bias + col);
                    float v0 = fmaxf(C[mt][nt][0] + bb.x, 0.f);
                    float v1 = fmaxf(C[mt][nt][1] + bb.y, 0.f);
                    float v2 = fmaxf(C[mt][nt][2] + bb.x, 0.f);
                    float v3 = fmaxf(C[mt][nt][3] + bb.y, 0.f);
                    *(__nv_bfloat162*)(Asm + row*AS + col)     = __floats2bfloat162_rn(v0, v1);
                    *(__nv_bfloat162*)(Asm + (row+8)*AS + col) = __floats2bfloat162_rn(v2, v3);
                }
            }
            // next chunk's post-wait __syncthreads orders these writes
        } else {
            // layer 4: bias + relu + column sum straight from fp32 registers
            float* stg = (float*)Asm;    // A tile dead; reuse as fp32 staging
            #pragma unroll
            for (int nt = 0; nt < 4; ++nt) {
                int col = wn*32 + nt*8 + (lane & 3)*2;
                float2 bb = *(const float2*)(b4 + col);
                float s0 = 0.f, s1 = 0.f;
                #pragma unroll
                for (int mt = 0; mt < 4; ++mt) {
                    s0 += fmaxf(C[mt][nt][0] + bb.x, 0.f)
                        + fmaxf(C[mt][nt][2] + bb.x, 0.f);
                    s1 += fmaxf(C[mt][nt][1] + bb.y, 0.f)
                        + fmaxf(C[mt][nt][3] + bb.y, 0.f);
                }
                #pragma unroll
                for (int off = 16; off >= 4; off >>= 1) {
                    s0 += __shfl_down_sync(0xffffffffu, s0, off);
                    s1 += __shfl_down_sync(0xffffffffu, s1, off);
                }
                if (lane < 4) {
                    int cc = wn*32 + nt*8 + lane*2;
                    stg[wm*GD + cc]     = s0;
                    stg[wm*GD + cc + 1] = s1;
                }
            }
            __syncthreads();
            if (tid < GD)
                d_partial[blockIdx.x*GD + tid] = stg[tid] + stg[GD + tid];
        }
    }
}

// ---------------------------------------------------------------------------
// rn_post: mean -> f-MLP -> log_softmax. grid 64, 1024 threads, k-split x4.
// ---------------------------------------------------------------------------
__global__ void __launch_bounds__(1024, 1)
rn_post(const float* __restrict__ fw1, const float* __restrict__ fb1,
        const float* __restrict__ fw2, const float* __restrict__ fb2,
        const float* __restrict__ fw3, const float* __restrict__ fb3,
        float* __restrict__ out) {
    __shared__ float ctx[GD], acc[1024], y1s[GD], y2s[GD], red[16];
    const int n   = blockIdx.x;
    const int t   = threadIdx.x;
    const int col = t & 255;
    const int q   = t >> 8;                        // k-quarter 0..3

    // mean of 32 partial tiles (8 per quarter)
    {
        const float* base = d_partial + (n*32 + q*8)*GD + col;
        float s = 0.f;
        #pragma unroll
        for (int p = 0; p < 8; ++p) s += base[p*GD];
        acc[t] = s;
    }
    __syncthreads();
    if (t < GD)
        ctx[t] = (acc[t] + acc[t+256] + acc[t+512] + acc[t+768]) * (1.0f/4096.0f);
    __syncthreads();

    // f1
    {
        float a0 = 0.f, a1 = 0.f;
        const float* w = fw1 + (q*64)*GD + col;
        #pragma unroll 8
        for (int k = 0; k < 64; k += 2) {
            a0 += ctx[q*64 + k]     * w[k*GD];
            a1 += ctx[q*64 + k + 1] * w[(k+1)*GD];
        }
        acc[t] = a0 + a1;
    }
    __syncthreads();
    if (t < GD)
        y1s[t] = fmaxf(acc[t] + acc[t+256] + acc[t+512] + acc[t+768] + fb1[t], 0.f);
    __syncthreads();

    // f2
    {
        float a0 = 0.f, a1 = 0.f;
        const float* w = fw2 + (q*64)*GD + col;
        #pragma unroll 8
        for (int k = 0; k < 64; k += 2) {
            a0 += y1s[q*64 + k]     * w[k*GD];
            a1 += y1s[q*64 + k + 1] * w[(k+1)*GD];
        }
        acc[t] = a0 + a1;
    }
    __syncthreads();
    if (t < GD)
        y2s[t] = fmaxf(acc[t] + acc[t+256] + acc[t+512] + acc[t+768] + fb2[t], 0.f);
    __syncthreads();

    // f3 + log_softmax
    if (t < GD) {
        float p0 = y2s[t] * fw3[t*2 + 0];
        float p1 = y2s[t] * fw3[t*2 + 1];
        #pragma unroll
        for (int o = 16; o > 0; o >>= 1) {
            p0 += __shfl_down_sync(0xffffffffu, p0, o);
            p1 += __shfl_down_sync(0xffffffffu, p1, o);
        }
        if ((t & 31) == 0) { red[t >> 5] = p0; red[8 + (t >> 5)] = p1; }
    }
    __syncthreads();
    if (t == 0) {
        float s0 = fb3[0], s1 = fb3[1];
        #pragma unroll
        for (int w = 0; w < 8; ++w) { s0 += red[w]; s1 += red[8 + w]; }
        float m   = fmaxf(s0, s1);
        float lse = m + logf(expf(s0 - m) + expf(s1 - m));
        out[n*2 + 0] = s0 - lse;
        out[n*2 + 1] = s1 - lse;
    }
}

// ---------------------------------------------------------------------------
extern "C" void kernel_launch(void* const* d_in, const int* in_sizes, int n_in,
                              void* d_out, int out_size) {
    (void)in_sizes; (void)n_in; (void)out_size;
    const float* img  = (const float*)d_in[0];
    const float* ques = (const float*)d_in[1];
    const float* gw1  = (const float*)d_in[2];
    const float* gb1  = (const float*)d_in[3];
    const float* gw2  = (const float*)d_in[4];
    const float* gb2  = (const float*)d_in[5];
    const float* gw3  = (const float*)d_in[6];
    const float* gb3  = (const float*)d_in[7];
    const float* gw4  = (const float*)d_in[8];
    const float* gb4  = (const float*)d_in[9];
    const float* fw1  = (const float*)d_in[10];
    const float* fb1  = (const float*)d_in[11];
    const float* fw2  = (const float*)d_in[12];
    const float* fb2  = (const float*)d_in[13];
    const float* fw3  = (const float*)d_in[14];
    const float* fb3  = (const float*)d_in[15];
    float* out = (float*)d_out;

    cudaFuncSetAttribute(rn_pre,  cudaFuncAttributeMaxDynamicSharedMemorySize, SM_PRE);
    cudaFuncSetAttribute(rn_main, cudaFuncAttributeMaxDynamicSharedMemorySize, SM_MAIN);

    rn_pre  <<<NB, 512, SM_PRE>>>(img, ques, gw1, gb1, gw2, gw3, gw4);
    rn_main <<<NCTA, 512, SM_MAIN>>>(gb2, gb3, gb4);
    rn_post <<<NB, 1024>>>(fw1, fb1, fw2, fb2, fw3, fb3, out);
}

// round 8
// speedup vs baseline: 2.2793x; 1.0689x over previous
#include <cuda_runtime.h>
#include <cuda_bf16.h>
#include <cstdint>

// ---------------------------------------------------------------------------
// RelNet forward, GB300 (sm_103a).
// h1(n,i,j) = relu(rowA[n,i] + rowB[n,j] + qc[n])  (layer-1 factorization)
// Layers 2-4: fused bf16 m16n8k16 MMA per 128-pair tile (proven occ-1 config),
// fp32 column sums -> mean -> parallel f-MLP -> log_softmax.
// ---------------------------------------------------------------------------

#define NB   64
#define OO   64
#define GD   256
#define DD   66
#define NCTA 2048                    // 64 batches * 32 row tiles (2 i x 64 j)
#define AS   264                     // bf16 elems per smem row (256 + 8 pad)
#define SM_MAIN (3*128*AS*2)         // A tile + 2 weight half-buffers (bytes)
#define SM_PRE  ((DD*256 + DD*64)*4) // 84480 B -> 2 CTAs/SM by resources

// --------------------------- device scratch --------------------------------
__device__ float d_rowA[NB*OO*GD];
__device__ float d_rowB[NB*OO*GD];
__device__ float d_qc  [NB*GD];
__device__ __nv_bfloat16 d_w2b[GD*GD];
__device__ __nv_bfloat16 d_w3b[GD*GD];
__device__ __nv_bfloat16 d_w4b[GD*GD];
__device__ float d_partial[NCTA*GD];

__device__ __forceinline__ void ldsm_x4(unsigned* r, unsigned addr) {
    asm volatile("ldmatrix.sync.aligned.m8n8.x4.shared.b16 {%0,%1,%2,%3}, [%4];"
                 : "=r"(r[0]), "=r"(r[1]), "=r"(r[2]), "=r"(r[3]) : "r"(addr));
}
__device__ __forceinline__ void ldsm_x4_t(unsigned* r, unsigned addr) {
    asm volatile("ldmatrix.sync.aligned.m8n8.x4.trans.shared.b16 {%0,%1,%2,%3}, [%4];"
                 : "=r"(r[0]), "=r"(r[1]), "=r"(r[2]), "=r"(r[3]) : "r"(addr));
}
__device__ __forceinline__ void mma_bf16(float* c, const unsigned* a,
                                         unsigned b0, unsigned b1) {
    asm volatile(
        "mma.sync.aligned.m16n8k16.row.col.f32.bf16.bf16.f32 "
        "{%0,%1,%2,%3}, {%4,%5,%6,%7}, {%8,%9}, {%0,%1,%2,%3};"
        : "+f"(c[0]), "+f"(c[1]), "+f"(c[2]), "+f"(c[3])
        : "r"(a[0]), "r"(a[1]), "r"(a[2]), "r"(a[3]), "r"(b0), "r"(b1));
}

// ---------------------------------------------------------------------------
// rn_pre: grid 192 x 512.
//   bx < 128 : rowA/rowB CTA. n = bx>>1, half = bx&1. Stages its own 66x256
//              weight slab (67.6 KB) -> natural 2 CTAs/SM. Each thread does
//              4 i-tiles of 8 objects (was 8 -> 2x more parallel).
//   bx >= 128: qc CTA (one per batch), k-split x2, 4-way ILP accumulators.
//   All 192 CTAs convert exactly one float2 of g-weights to bf16 (98304 total).
// ---------------------------------------------------------------------------
__global__ void __launch_bounds__(512)
rn_pre(const float* __restrict__ img, const float* __restrict__ ques,
       const float* __restrict__ gw1, const float* __restrict__ gb1,
       const float* __restrict__ w2, const float* __restrict__ w3,
       const float* __restrict__ w4) {
    extern __shared__ float fsm[];
    const int bx = blockIdx.x;
    const int t  = threadIdx.x;

    // weight fp32->bf16 conversion: 192*512 threads, one float2 each.
    {
        const int gt = bx*512 + t;                // 0 .. 98303
        int m   = gt >> 15;                       // 0..2
        int off = (gt & 32767) * 2;
        const float* src = (m == 0) ? w2 : (m == 1) ? w3 : w4;
        __nv_bfloat16* dst = (m == 0) ? d_w2b : (m == 1) ? d_w3b : d_w4b;
        float2 v = *(const float2*)(src + off);
        *(__nv_bfloat162*)(dst + off) = __floats2bfloat162_rn(v.x, v.y);
    }

    if (bx < 128) {
        float* wsm = fsm;                 // [66][256]
        float* csm = fsm + DD*256;        // [66][64]
        const int n    = bx >> 1;
        const int half = bx & 1;

        const float4* wsrc = (const float4*)(gw1 + half*DD*256);
        for (int i = t; i < DD*256/4; i += 512)
            ((float4*)wsm)[i] = wsrc[i];
        for (int idx = t; idx < DD*OO; idx += 512) {
            int d = idx >> 6, i = idx & 63;
            float v;
            if (d < 64)       v = img[(n*64 + d)*64 + i];
            else if (d == 64) v = (float)(i >> 3);
            else              v = (float)(i & 7);
            csm[d*64 + i] = v;
        }
        __syncthreads();

        const int g   = t & 255;
        const int ith = t >> 8;                   // 0..1
        float* out = half ? d_rowB : d_rowA;

        #pragma unroll 1
        for (int it4 = 0; it4 < 4; ++it4) {
            const int it = ith*4 + it4;           // 0..7
            float acc[8];
            #pragma unroll
            for (int ii = 0; ii < 8; ++ii) acc[ii] = 0.f;
            #pragma unroll 2
            for (int d = 0; d < DD; ++d) {
                float w = wsm[d*256 + g];
                #pragma unroll
                for (int ii = 0; ii < 8; ++ii)
                    acc[ii] += csm[d*64 + it*8 + ii] * w;
            }
            #pragma unroll
            for (int ii = 0; ii < 8; ++ii)
                out[(n*OO + it*8 + ii)*GD + g] = acc[ii];
        }
    } else {
        // qc CTA: qc[n] = ques[n] @ gw1[132:388] + gb1
        float* qsm = fsm;                 // [256]
        float* red = fsm + 256;           // [2][256]
        const int n  = bx - 128;
        const int ks = t >> 8;            // k-half 0..1
        const int g  = t & 255;

        if (t < 256) qsm[t] = ques[n*GD + t];
        __syncthreads();

        const float* base = gw1 + (2*DD + ks*128)*GD + g;
        const float* qb   = qsm + ks*128;
        float a0 = 0.f, a1 = 0.f, a2 = 0.f, a3 = 0.f;
        #pragma unroll 8
        for (int e = 0; e < 128; e += 4) {
            a0 += qb[e]     * base[(e)    *GD];
            a1 += qb[e + 1] * base[(e + 1)*GD];
            a2 += qb[e + 2] * base[(e + 2)*GD];
            a3 += qb[e + 3] * base[(e + 3)*GD];
        }
        red[ks*256 + g] = (a0 + a1) + (a2 + a3);
        __syncthreads();
        if (t < 256)
            d_qc[n*GD + t] = red[t] + red[256 + t] + gb1[t];
    }
}

// ---------------------------------------------------------------------------
// rn_main: fused layers 2-4 per 128-pair tile. grid 2048, 512 threads.
// A tile 128x256 bf16 in smem; weights double-buffered in k=128 halves.
// Warp grid 2x8, warp tile 64x32, mma m16n8k16 bf16 via ldmatrix.
// (Proven configuration — unchanged from the 370.8us run.)
// ---------------------------------------------------------------------------
__global__ void __launch_bounds__(512, 1)
rn_main(const float* __restrict__ b2, const float* __restrict__ b3,
        const float* __restrict__ b4) {
    extern __shared__ __nv_bfloat16 sm[];
    __nv_bfloat16* Asm = sm;                      // [128][AS]
    __nv_bfloat16* Bsm = sm + 128*AS;             // 2 x [128][AS]
    const unsigned AsmS = (unsigned)__cvta_generic_to_shared(Asm);
    const unsigned BsmS = (unsigned)__cvta_generic_to_shared(Bsm);

    const int n    = blockIdx.x >> 5;
    const int i0   = (blockIdx.x & 31) << 1;
    const int tid  = threadIdx.x;
    const int lane = tid & 31;
    const int warp = tid >> 5;
    const int wm   = warp >> 3;                   // 0..1 -> 64-row block
    const int wn   = warp & 7;                    // 0..7 -> 32-col block

    // chunk c (0..5): layer c/2, k-half c&1
    auto issue = [&](int c) {
        const __nv_bfloat16* W = (c < 2) ? d_w2b : (c < 4) ? d_w3b : d_w4b;
        const __nv_bfloat16* src = W + (c & 1) * 128 * GD;
        unsigned dst = BsmS + (unsigned)((c & 1) * 128 * AS * 2);
        #pragma unroll
        for (int q = 0; q < 8; ++q) {
            int idx = q * 512 + tid;
            int r = idx >> 5, s = idx & 31;
            unsigned sa = dst + (unsigned)(r * AS + s * 8) * 2u;
            asm volatile("cp.async.cg.shared.global [%0], [%1], 16;"
                         :: "r"(sa), "l"(src + r * GD + s * 8));
        }
        asm volatile("cp.async.commit_group;");
    };

    issue(0);   // prefetch first weight half while building h1

    // ---- stage 1: h1 = relu(rowA_i + rowB_j + qc) -> bf16 A tile ----
    {
        const int g  = (tid & 127) * 2;
        const int r0 = tid >> 7;                  // 0..3
        const float2 qv = *(const float2*)(d_qc + n*GD + g);
        float2 A0 = *(const float2*)(d_rowA + (n*OO + i0    )*GD + g);
        float2 A1 = *(const float2*)(d_rowA + (n*OO + i0 + 1)*GD + g);
        A0.x += qv.x; A0.y += qv.y; A1.x += qv.x; A1.y += qv.y;
        #pragma unroll 4
        for (int s = 0; s < 32; ++s) {
            int r = r0 + s*4;
            int j = r & 63;
            float2 B = *(const float2*)(d_rowB + (n*OO + j)*GD + g);
            float vx = ((r >> 6) ? A1.x : A0.x) + B.x;
            float vy = ((r >> 6) ? A1.y : A0.y) + B.y;
            *(__nv_bfloat162*)(Asm + r*AS + g) =
                __floats2bfloat162_rn(fmaxf(vx, 0.f), fmaxf(vy, 0.f));
        }
    }

    #pragma unroll 1
    for (int layer = 0; layer < 3; ++layer) {
        float C[4][4][4];
        #pragma unroll
        for (int mt = 0; mt < 4; ++mt)
            #pragma unroll
            for (int nt = 0; nt < 4; ++nt) {
                C[mt][nt][0] = 0.f; C[mt][nt][1] = 0.f;
                C[mt][nt][2] = 0.f; C[mt][nt][3] = 0.f;
            }

        #pragma unroll 1
        for (int h = 0; h < 2; ++h) {
            const int c = layer*2 + h;
            if (c < 5) { issue(c + 1); asm volatile("cp.async.wait_group 1;"); }
            else       {               asm volatile("cp.async.wait_group 0;"); }
            __syncthreads();            // chunk c ready; orders A-tile writes

            const unsigned bufS = BsmS + (unsigned)((c & 1) * 128 * AS * 2);
            #pragma unroll
            for (int ks = 0; ks < 8; ++ks) {
                const int kb = h*128 + ks*16;
                unsigned a[4][4];
                #pragma unroll
                for (int mt = 0; mt < 4; ++mt) {
                    unsigned ad = AsmS +
                        (unsigned)(((wm*64 + mt*16 + (lane & 15)))*AS
                                   + kb + ((lane >> 4) * 8)) * 2u;
                    ldsm_x4(a[mt], ad);
                }
                unsigned bfr[2][4];
                #pragma unroll
                for (int pr = 0; pr < 2; ++pr) {
                    unsigned bd = bufS +
                        (unsigned)((ks*16 + (lane & 15))*AS
                                   + wn*32 + pr*16 + ((lane >> 4) * 8)) * 2u;
                    ldsm_x4_t(bfr[pr], bd);
                }
                #pragma unroll
                for (int mt = 0; mt < 4; ++mt) {
                    #pragma unroll
                    for (int pr = 0; pr < 2; ++pr) {
                        mma_bf16(C[mt][pr*2    ], a[mt], bfr[pr][0], bfr[pr][1]);
                        mma_bf16(C[mt][pr*2 + 1], a[mt], bfr[pr][2], bfr[pr][3]);
                    }
                }
            }
            __syncthreads();            // all reads of buf c / A done
        }

        if (layer < 2) {
            // epilogue: bias + relu -> bf16, in place into A tile
            const float* bias = (layer == 0) ? b2 : b3;
            #pragma unroll
            for (int mt = 0; mt < 4; ++mt) {
                #pragma unroll
                for (int nt = 0; nt < 4; ++nt) {
                    int row = wm*64 + mt*16 + (lane >> 2);
                    int col = wn*32 + nt*8 + (lane & 3)*2;
                    float2 bb = *(const float2*)(bias + col);
                    float v0 = fmaxf(C[mt][nt][0] + bb.x, 0.f);
                    float v1 = fmaxf(C[mt][nt][1] + bb.y, 0.f);
                    float v2 = fmaxf(C[mt][nt][2] + bb.x, 0.f);
                    float v3 = fmaxf(C[mt][nt][3] + bb.y, 0.f);
                    *(__nv_bfloat162*)(Asm + row*AS + col)     = __floats2bfloat162_rn(v0, v1);
                    *(__nv_bfloat162*)(Asm + (row+8)*AS + col) = __floats2bfloat162_rn(v2, v3);
                }
            }
            // next chunk's post-wait __syncthreads orders these writes
        } else {
            // layer 4: bias + relu + column sum straight from fp32 registers
            float* stg = (float*)Asm;    // A tile dead; reuse as fp32 staging
            #pragma unroll
            for (int nt = 0; nt < 4; ++nt) {
                int col = wn*32 + nt*8 + (lane & 3)*2;
                float2 bb = *(const float2*)(b4 + col);
                float s0 = 0.f, s1 = 0.f;
                #pragma unroll
                for (int mt = 0; mt < 4; ++mt) {
                    s0 += fmaxf(C[mt][nt][0] + bb.x, 0.f)
                        + fmaxf(C[mt][nt][2] + bb.x, 0.f);
                    s1 += fmaxf(C[mt][nt][1] + bb.y, 0.f)
                        + fmaxf(C[mt][nt][3] + bb.y, 0.f);
                }
                #pragma unroll
                for (int off = 16; off >= 4; off >>= 1) {
                    s0 += __shfl_down_sync(0xffffffffu, s0, off);
                    s1 += __shfl_down_sync(0xffffffffu, s1, off);
                }
                if (lane < 4) {
                    int cc = wn*32 + nt*8 + lane*2;
                    stg[wm*GD + cc]     = s0;
                    stg[wm*GD + cc + 1] = s1;
                }
            }
            __syncthreads();
            if (tid < GD)
                d_partial[blockIdx.x*GD + tid] = stg[tid] + stg[GD + tid];
        }
    }
}

// ---------------------------------------------------------------------------
// rn_post: mean -> f-MLP -> log_softmax. grid 64, 1024 threads, k-split x4.
// ---------------------------------------------------------------------------
__global__ void __launch_bounds__(1024, 1)
rn_post(const float* __restrict__ fw1, const float* __restrict__ fb1,
        const float* __restrict__ fw2, const float* __restrict__ fb2,
        const float* __restrict__ fw3, const float* __restrict__ fb3,
        float* __restrict__ out) {
    __shared__ float ctx[GD], acc[1024], y1s[GD], y2s[GD], red[16];
    const int n   = blockIdx.x;
    const int t   = threadIdx.x;
    const int col = t & 255;
    const int q   = t >> 8;                        // k-quarter 0..3

    // mean of 32 partial tiles (8 per quarter)
    {
        const float* base = d_partial + (n*32 + q*8)*GD + col;
        float s = 0.f;
        #pragma unroll
        for (int p = 0; p < 8; ++p) s += base[p*GD];
        acc[t] = s;
    }
    __syncthreads();
    if (t < GD)
        ctx[t] = (acc[t] + acc[t+256] + acc[t+512] + acc[t+768]) * (1.0f/4096.0f);
    __syncthreads();

    // f1
    {
        float a0 = 0.f, a1 = 0.f;
        const float* w = fw1 + (q*64)*GD + col;
        #pragma unroll 8
        for (int k = 0; k < 64; k += 2) {
            a0 += ctx[q*64 + k]     * w[k*GD];
            a1 += ctx[q*64 + k + 1] * w[(k+1)*GD];
        }
        acc[t] = a0 + a1;
    }
    __syncthreads();
    if (t < GD)
        y1s[t] = fmaxf(acc[t] + acc[t+256] + acc[t+512] + acc[t+768] + fb1[t], 0.f);
    __syncthreads();

    // f2
    {
        float a0 = 0.f, a1 = 0.f;
        const float* w = fw2 + (q*64)*GD + col;
        #pragma unroll 8
        for (int k = 0; k < 64; k += 2) {
            a0 += y1s[q*64 + k]     * w[k*GD];
            a1 += y1s[q*64 + k + 1] * w[(k+1)*GD];
        }
        acc[t] = a0 + a1;
    }
    __syncthreads();
    if (t < GD)
        y2s[t] = fmaxf(acc[t] + acc[t+256] + acc[t+512] + acc[t+768] + fb2[t], 0.f);
    __syncthreads();

    // f3 + log_softmax
    if (t < GD) {
        float p0 = y2s[t] * fw3[t*2 + 0];
        float p1 = y2s[t] * fw3[t*2 + 1];
        #pragma unroll
        for (int o = 16; o > 0; o >>= 1) {
            p0 += __shfl_down_sync(0xffffffffu, p0, o);
            p1 += __shfl_down_sync(0xffffffffu, p1, o);
        }
        if ((t & 31) == 0) { red[t >> 5] = p0; red[8 + (t >> 5)] = p1; }
    }
    __syncthreads();
    if (t == 0) {
        float s0 = fb3[0], s1 = fb3[1];
        #pragma unroll
        for (int w = 0; w < 8; ++w) { s0 += red[w]; s1 += red[8 + w]; }
        float m   = fmaxf(s0, s1);
        float lse = m + logf(expf(s0 - m) + expf(s1 - m));
        out[n*2 + 0] = s0 - lse;
        out[n*2 + 1] = s1 - lse;
    }
}

// ---------------------------------------------------------------------------
extern "C" void kernel_launch(void* const* d_in, const int* in_sizes, int n_in,
                              void* d_out, int out_size) {
    (void)in_sizes; (void)n_in; (void)out_size;
    const float* img  = (const float*)d_in[0];
    const float* ques = (const float*)d_in[1];
    const float* gw1  = (const float*)d_in[2];
    const float* gb1  = (const float*)d_in[3];
    const float* gw2  = (const float*)d_in[4];
    const float* gb2  = (const float*)d_in[5];
    const float* gw3  = (const float*)d_in[6];
    const float* gb3  = (const float*)d_in[7];
    const float* gw4  = (const float*)d_in[8];
    const float* gb4  = (const float*)d_in[9];
    const float* fw1  = (const float*)d_in[10];
    const float* fb1  = (const float*)d_in[11];
    const float* fw2  = (const float*)d_in[12];
    const float* fb2  = (const float*)d_in[13];
    const float* fw3  = (const float*)d_in[14];
    const float* fb3  = (const float*)d_in[15];
    float* out = (float*)d_out;

    cudaFuncSetAttribute(rn_pre,  cudaFuncAttributeMaxDynamicSharedMemorySize, SM_PRE);
    cudaFuncSetAttribute(rn_main, cudaFuncAttributeMaxDynamicSharedMemorySize, SM_MAIN);

    rn_pre  <<<192, 512, SM_PRE>>>(img, ques, gw1, gb1, gw2, gw3, gw4);
    rn_main <<<NCTA, 512, SM_MAIN>>>(gb2, gb3, gb4);
    rn_post <<<NB, 1024>>>(fw1, fb1, fw2, fb2, fw3, fb3, out);
}

// round 9
// speedup vs baseline: 2.2934x; 1.0062x over previous
#include <cuda_runtime.h>
#include <cuda_bf16.h>
#include <cstdint>

// ---------------------------------------------------------------------------
// RelNet forward, GB300 (sm_103a).
// h1(n,i,j) = relu(rowA[n,i] + rowB[n,j] + qc[n])  (layer-1 factorization)
// Layers 2-4: fused bf16 m16n8k16 MMA per 64-pair tile, 2 CTAs/SM.
// fp32 column sums -> mean -> parallel f-MLP -> log_softmax.
// ---------------------------------------------------------------------------

#define NB   64
#define OO   64
#define GD   256
#define DD   66
#define NCTA 4096                    // 64 batches * 64 i-rows
#define AS   264                     // bf16 elems per smem row (256 + 8 pad)
#define KC   64                      // weight rows per cp.async chunk
#define SM_MAIN ((64*AS + 2*KC*AS)*2)          // 101376 B -> 2 CTAs/SM
#define SM_PRE  ((DD*256 + DD*64)*4)           // 84480 B  -> 2 CTAs/SM

// --------------------------- device scratch --------------------------------
__device__ float d_rowA[NB*OO*GD];
__device__ float d_rowB[NB*OO*GD];
__device__ float d_qc  [NB*GD];
__device__ __nv_bfloat16 d_w2b[GD*GD];
__device__ __nv_bfloat16 d_w3b[GD*GD];
__device__ __nv_bfloat16 d_w4b[GD*GD];
__device__ float d_partial[NCTA*GD];

__device__ __forceinline__ void ldsm_x4(unsigned* r, unsigned addr) {
    asm volatile("ldmatrix.sync.aligned.m8n8.x4.shared.b16 {%0,%1,%2,%3}, [%4];"
                 : "=r"(r[0]), "=r"(r[1]), "=r"(r[2]), "=r"(r[3]) : "r"(addr));
}
__device__ __forceinline__ void ldsm_x4_t(unsigned* r, unsigned addr) {
    asm volatile("ldmatrix.sync.aligned.m8n8.x4.trans.shared.b16 {%0,%1,%2,%3}, [%4];"
                 : "=r"(r[0]), "=r"(r[1]), "=r"(r[2]), "=r"(r[3]) : "r"(addr));
}
__device__ __forceinline__ void mma_bf16(float* c, const unsigned* a,
                                         unsigned b0, unsigned b1) {
    asm volatile(
        "mma.sync.aligned.m16n8k16.row.col.f32.bf16.bf16.f32 "
        "{%0,%1,%2,%3}, {%4,%5,%6,%7}, {%8,%9}, {%0,%1,%2,%3};"
        : "+f"(c[0]), "+f"(c[1]), "+f"(c[2]), "+f"(c[3])
        : "r"(a[0]), "r"(a[1]), "r"(a[2]), "r"(a[3]), "r"(b0), "r"(b1));
}

// ---------------------------------------------------------------------------
// rn_pre: grid 320 x 512.
//   bx < 256 : rowA/rowB CTA. n = bx>>2, half = (bx>>1)&1, ihalf = bx&1.
//              Stages its 66x256 weight slab (67.6 KB) -> 2 CTAs/SM.
//              Each thread computes 2 i-tiles; cell reads vectorized (float4).
//   bx >= 256: qc CTA (one per batch), k-split x2, 4-way ILP accumulators.
//   First 192 CTAs also convert one float2 of g-weights to bf16 each.
// ---------------------------------------------------------------------------
__global__ void __launch_bounds__(512)
rn_pre(const float* __restrict__ img, const float* __restrict__ ques,
       const float* __restrict__ gw1, const float* __restrict__ gb1,
       const float* __restrict__ w2, const float* __restrict__ w3,
       const float* __restrict__ w4) {
    extern __shared__ float fsm[];
    const int bx = blockIdx.x;
    const int t  = threadIdx.x;

    // weight fp32->bf16 conversion (98304 float2 over first 192 CTAs)
    {
        const int gt = bx*512 + t;
        if (gt < 3*32768) {
            int m   = gt >> 15;
            int off = (gt & 32767) * 2;
            const float* src = (m == 0) ? w2 : (m == 1) ? w3 : w4;
            __nv_bfloat16* dst = (m == 0) ? d_w2b : (m == 1) ? d_w3b : d_w4b;
            float2 v = *(const float2*)(src + off);
            *(__nv_bfloat162*)(dst + off) = __floats2bfloat162_rn(v.x, v.y);
        }
    }

    if (bx < 256) {
        float* wsm = fsm;                 // [66][256]
        float* csm = fsm + DD*256;        // [66][64]
        const int n     = bx >> 2;
        const int half  = (bx >> 1) & 1;
        const int ihalf = bx & 1;

        const float4* wsrc = (const float4*)(gw1 + half*DD*256);
        for (int i = t; i < DD*256/4; i += 512)
            ((float4*)wsm)[i] = wsrc[i];
        for (int idx = t; idx < DD*OO; idx += 512) {
            int d = idx >> 6, i = idx & 63;
            float v;
            if (d < 64)       v = img[(n*64 + d)*64 + i];
            else if (d == 64) v = (float)(i >> 3);
            else              v = (float)(i & 7);
            csm[d*64 + i] = v;
        }
        __syncthreads();

        const int g   = t & 255;
        const int ith = t >> 8;                   // 0..1
        float* out = half ? d_rowB : d_rowA;

        #pragma unroll
        for (int it2 = 0; it2 < 2; ++it2) {
            const int it = ihalf*4 + ith*2 + it2; // 0..7
            float acc[8];
            #pragma unroll
            for (int ii = 0; ii < 8; ++ii) acc[ii] = 0.f;
            #pragma unroll 2
            for (int d = 0; d < DD; ++d) {
                float w = wsm[d*256 + g];
                float4 c0 = *(const float4*)(csm + d*64 + it*8);
                float4 c1 = *(const float4*)(csm + d*64 + it*8 + 4);
                acc[0] += c0.x * w; acc[1] += c0.y * w;
                acc[2] += c0.z * w; acc[3] += c0.w * w;
                acc[4] += c1.x * w; acc[5] += c1.y * w;
                acc[6] += c1.z * w; acc[7] += c1.w * w;
            }
            #pragma unroll
            for (int ii = 0; ii < 8; ++ii)
                out[(n*OO + it*8 + ii)*GD + g] = acc[ii];
        }
    } else {
        // qc CTA: qc[n] = ques[n] @ gw1[132:388] + gb1
        float* qsm = fsm;                 // [256]
        float* red = fsm + 256;           // [2][256]
        const int n  = bx - 256;
        const int ks = t >> 8;            // k-half 0..1
        const int g  = t & 255;

        if (t < 256) qsm[t] = ques[n*GD + t];
        __syncthreads();

        const float* base = gw1 + (2*DD + ks*128)*GD + g;
        const float* qb   = qsm + ks*128;
        float a0 = 0.f, a1 = 0.f, a2 = 0.f, a3 = 0.f;
        #pragma unroll 8
        for (int e = 0; e < 128; e += 4) {
            a0 += qb[e]     * base[(e)    *GD];
            a1 += qb[e + 1] * base[(e + 1)*GD];
            a2 += qb[e + 2] * base[(e + 2)*GD];
            a3 += qb[e + 3] * base[(e + 3)*GD];
        }
        red[ks*256 + g] = (a0 + a1) + (a2 + a3);
        __syncthreads();
        if (t < 256)
            d_qc[n*GD + t] = red[t] + red[256 + t] + gb1[t];
    }
}

// ---------------------------------------------------------------------------
// rn_main: fused layers 2-4 per 64-pair tile (one i, 64 j).
// grid 4096, 256 threads, 2 CTAs/SM. Warp grid 2x4, warp tile 32x64.
// ---------------------------------------------------------------------------
__global__ void __launch_bounds__(256, 2)
rn_main(const float* __restrict__ b2, const float* __restrict__ b3,
        const float* __restrict__ b4) {
    extern __shared__ __nv_bfloat16 sm[];
    __nv_bfloat16* Asm = sm;                      // [64][AS]
    const unsigned AsmS = (unsigned)__cvta_generic_to_shared(sm);
    const unsigned BsmS = AsmS + (unsigned)(64*AS*2);

    const int n    = blockIdx.x >> 6;
    const int i0   = blockIdx.x & 63;
    const int tid  = threadIdx.x;
    const int lane = tid & 31;
    const int warp = tid >> 5;
    const int wm   = warp >> 2;                   // 0..1 -> 32-row block
    const int wn   = warp & 3;                    // 0..3 -> 64-col block

    // chunk c (0..11): layer c/4, k-quarter c&3 (KC=64 rows per chunk)
    auto issue = [&](int c) {
        const __nv_bfloat16* W = (c < 4) ? d_w2b : (c < 8) ? d_w3b : d_w4b;
        const __nv_bfloat16* src = W + (c & 3) * KC * GD;
        unsigned dst = BsmS + (unsigned)((c & 1) * KC * AS * 2);
        #pragma unroll
        for (int q = 0; q < 8; ++q) {
            int idx = q * 256 + tid;
            int r = idx >> 5, s = idx & 31;
            unsigned sa = dst + (unsigned)(r * AS + s * 8) * 2u;
            asm volatile("cp.async.cg.shared.global [%0], [%1], 16;"
                         :: "r"(sa), "l"(src + r * GD + s * 8));
        }
        asm volatile("cp.async.commit_group;");
    };

    issue(0);

    // ---- stage 1: h1 row-tile = relu(rowA[i0] + rowB[j] + qc), j = row ----
    {
        const int g  = (tid & 127) * 2;
        const int r0 = tid >> 7;                  // 0..1
        float2 qv = *(const float2*)(d_qc + n*GD + g);
        float2 A0 = *(const float2*)(d_rowA + (n*OO + i0)*GD + g);
        A0.x += qv.x; A0.y += qv.y;
        #pragma unroll 4
        for (int s = 0; s < 32; ++s) {
            int r = r0 + 2*s;                     // = j
            float2 B = *(const float2*)(d_rowB + (n*OO + r)*GD + g);
            *(__nv_bfloat162*)(Asm + r*AS + g) =
                __floats2bfloat162_rn(fmaxf(A0.x + B.x, 0.f),
                                      fmaxf(A0.y + B.y, 0.f));
        }
    }

    #pragma unroll 1
    for (int layer = 0; layer < 3; ++layer) {
        float C[2][8][4];
        #pragma unroll
        for (int mt = 0; mt < 2; ++mt)
            #pragma unroll
            for (int nt = 0; nt < 8; ++nt) {
                C[mt][nt][0] = 0.f; C[mt][nt][1] = 0.f;
                C[mt][nt][2] = 0.f; C[mt][nt][3] = 0.f;
            }

        #pragma unroll 1
        for (int ch = 0; ch < 4; ++ch) {
            const int c = layer*4 + ch;
            if (c < 11) { issue(c + 1); asm volatile("cp.async.wait_group 1;"); }
            else        {               asm volatile("cp.async.wait_group 0;"); }
            __syncthreads();          // chunk c ready; also orders A-tile writes

            const unsigned bufS = BsmS + (unsigned)((c & 1) * KC * AS * 2);
            #pragma unroll
            for (int ksl = 0; ksl < 4; ++ksl) {
                const int kg = ch*KC + ksl*16;
                unsigned a[2][4];
                #pragma unroll
                for (int mt = 0; mt < 2; ++mt) {
                    unsigned ad = AsmS +
                        (unsigned)((wm*32 + mt*16 + (lane & 15))*AS
                                   + kg + ((lane >> 4) * 8)) * 2u;
                    ldsm_x4(a[mt], ad);
                }
                unsigned bfr[4][4];
                #pragma unroll
                for (int pr = 0; pr < 4; ++pr) {
                    unsigned bd = bufS +
                        (unsigned)((ksl*16 + (lane & 15))*AS
                                   + wn*64 + pr*16 + ((lane >> 4) * 8)) * 2u;
                    ldsm_x4_t(bfr[pr], bd);
                }
                #pragma unroll
                for (int mt = 0; mt < 2; ++mt) {
                    #pragma unroll
                    for (int pr = 0; pr < 4; ++pr) {
                        mma_bf16(C[mt][pr*2    ], a[mt], bfr[pr][0], bfr[pr][1]);
                        mma_bf16(C[mt][pr*2 + 1], a[mt], bfr[pr][2], bfr[pr][3]);
                    }
                }
            }
            __syncthreads();          // reads of buf c / A tile done
        }

        if (layer < 2) {
            const float* bias = (layer == 0) ? b2 : b3;
            #pragma unroll
            for (int mt = 0; mt < 2; ++mt) {
                #pragma unroll
                for (int nt = 0; nt < 8; ++nt) {
                    int row = wm*32 + mt*16 + (lane >> 2);
                    int col = wn*64 + nt*8 + (lane & 3)*2;
                    float2 bb = *(const float2*)(bias + col);
                    float v0 = fmaxf(C[mt][nt][0] + bb.x, 0.f);
                    float v1 = fmaxf(C[mt][nt][1] + bb.y, 0.f);
                    float v2 = fmaxf(C[mt][nt][2] + bb.x, 0.f);
                    float v3 = fmaxf(C[mt][nt][3] + bb.y, 0.f);
                    *(__nv_bfloat162*)(Asm + row*AS + col)     = __floats2bfloat162_rn(v0, v1);
                    *(__nv_bfloat162*)(Asm + (row+8)*AS + col) = __floats2bfloat162_rn(v2, v3);
                }
            }
            // next chunk's post-wait __syncthreads orders these writes
        } else {
            // layer 4: bias + relu + column sum straight from fp32 registers
            float* stg = (float*)sm;              // A tile dead; fp32 staging
            #pragma unroll
            for (int nt = 0; nt < 8; ++nt) {
                int col = wn*64 + nt*8 + (lane & 3)*2;
                float2 bb = *(const float2*)(b4 + col);
                float s0 = 0.f, s1 = 0.f;
                #pragma unroll
                for (int mt = 0; mt < 2; ++mt) {
                    s0 += fmaxf(C[mt][nt][0] + bb.x, 0.f)
                        + fmaxf(C[mt][nt][2] + bb.x, 0.f);
                    s1 += fmaxf(C[mt][nt][1] + bb.y, 0.f)
                        + fmaxf(C[mt][nt][3] + bb.y, 0.f);
                }
                #pragma unroll
                for (int off = 16; off >= 4; off >>= 1) {
                    s0 += __shfl_down_sync(0xffffffffu, s0, off);
                    s1 += __shfl_down_sync(0xffffffffu, s1, off);
                }
                if (lane < 4) {
                    int cc = wn*64 + nt*8 + lane*2;
                    stg[wm*GD + cc]     = s0;
                    stg[wm*GD + cc + 1] = s1;
                }
            }
            __syncthreads();
            if (tid < GD)
                d_partial[blockIdx.x*GD + tid] = stg[tid] + stg[GD + tid];
        }
    }
}

// ---------------------------------------------------------------------------
// rn_post: mean -> f-MLP -> log_softmax. grid 64, 1024 threads, k-split x4.
// ---------------------------------------------------------------------------
__global__ void __launch_bounds__(1024, 1)
rn_post(const float* __restrict__ fw1, const float* __restrict__ fb1,
        const float* __restrict__ fw2, const float* __restrict__ fb2,
        const float* __restrict__ fw3, const float* __restrict__ fb3,
        float* __restrict__ out) {
    __shared__ float ctx[GD], acc[1024], y1s[GD], y2s[GD], red[16];
    const int n   = blockIdx.x;
    const int t   = threadIdx.x;
    const int col = t & 255;
    const int q   = t >> 8;                        // k-quarter 0..3

    // mean of 64 partial tiles (16 per quarter)
    {
        const float* base = d_partial + (n*64 + q*16)*GD + col;
        float s = 0.f;
        #pragma unroll
        for (int p = 0; p < 16; ++p) s += base[p*GD];
        acc[t] = s;
    }
    __syncthreads();
    if (t < GD)
        ctx[t] = (acc[t] + acc[t+256] + acc[t+512] + acc[t+768]) * (1.0f/4096.0f);
    __syncthreads();

    // f1
    {
        float a0 = 0.f, a1 = 0.f;
        const float* w = fw1 + (q*64)*GD + col;
        #pragma unroll 8
        for (int k = 0; k < 64; k += 2) {
            a0 += ctx[q*64 + k]     * w[k*GD];
            a1 += ctx[q*64 + k + 1] * w[(k+1)*GD];
        }
        acc[t] = a0 + a1;
    }
    __syncthreads();
    if (t < GD)
        y1s[t] = fmaxf(acc[t] + acc[t+256] + acc[t+512] + acc[t+768] + fb1[t], 0.f);
    __syncthreads();

    // f2
    {
        float a0 = 0.f, a1 = 0.f;
        const float* w = fw2 + (q*64)*GD + col;
        #pragma unroll 8
        for (int k = 0; k < 64; k += 2) {
            a0 += y1s[q*64 + k]     * w[k*GD];
            a1 += y1s[q*64 + k + 1] * w[(k+1)*GD];
        }
        acc[t] = a0 + a1;
    }
    __syncthreads();
    if (t < GD)
        y2s[t] = fmaxf(acc[t] + acc[t+256] + acc[t+512] + acc[t+768] + fb2[t], 0.f);
    __syncthreads();

    // f3 + log_softmax
    if (t < GD) {
        float p0 = y2s[t] * fw3[t*2 + 0];
        float p1 = y2s[t] * fw3[t*2 + 1];
        #pragma unroll
        for (int o = 16; o > 0; o >>= 1) {
            p0 += __shfl_down_sync(0xffffffffu, p0, o);
            p1 += __shfl_down_sync(0xffffffffu, p1, o);
        }
        if ((t & 31) == 0) { red[t >> 5] = p0; red[8 + (t >> 5)] = p1; }
    }
    __syncthreads();
    if (t == 0) {
        float s0 = fb3[0], s1 = fb3[1];
        #pragma unroll
        for (int w = 0; w < 8; ++w) { s0 += red[w]; s1 += red[8 + w]; }
        float m   = fmaxf(s0, s1);
        float lse = m + logf(expf(s0 - m) + expf(s1 - m));
        out[n*2 + 0] = s0 - lse;
        out[n*2 + 1] = s1 - lse;
    }
}

// ---------------------------------------------------------------------------
extern "C" void kernel_launch(void* const* d_in, const int* in_sizes, int n_in,
                              void* d_out, int out_size) {
    (void)in_sizes; (void)n_in; (void)out_size;
    const float* img  = (const float*)d_in[0];
    const float* ques = (const float*)d_in[1];
    const float* gw1  = (const float*)d_in[2];
    const float* gb1  = (const float*)d_in[3];
    const float* gw2  = (const float*)d_in[4];
    const float* gb2  = (const float*)d_in[5];
    const float* gw3  = (const float*)d_in[6];
    const float* gb3  = (const float*)d_in[7];
    const float* gw4  = (const float*)d_in[8];
    const float* gb4  = (const float*)d_in[9];
    const float* fw1  = (const float*)d_in[10];
    const float* fb1  = (const float*)d_in[11];
    const float* fw2  = (const float*)d_in[12];
    const float* fb2  = (const float*)d_in[13];
    const float* fw3  = (const float*)d_in[14];
    const float* fb3  = (const float*)d_in[15];
    float* out = (float*)d_out;

    cudaFuncSetAttribute(rn_pre,  cudaFuncAttributeMaxDynamicSharedMemorySize, SM_PRE);
    cudaFuncSetAttribute(rn_main, cudaFuncAttributeMaxDynamicSharedMemorySize, SM_MAIN);

    rn_pre  <<<320, 512, SM_PRE>>>(img, ques, gw1, gb1, gw2, gw3, gw4);
    rn_main <<<NCTA, 256, SM_MAIN>>>(gb2, gb3, gb4);
    rn_post <<<NB, 1024>>>(fw1, fb1, fw2, fb2, fw3, fb3, out);
}